// round 12
// baseline (speedup 1.0000x reference)
#include <cuda_runtime.h>
#include <cuda_bf16.h>
#include <cstdint>

// MHSA with RPE bias.  B=256, N=196, C=784, H=4, D=196.
// Round 12: proj -> 4-stage cp.async pipeline with BK=16 (784 = 49*16, no
// tail); attention -> dead-tile guards (skip mma for fully-padded slabs).

namespace {
constexpr int B_ = 256, N_ = 196, C_ = 784, H_ = 4, D_ = 196;
constexpr int M_ = B_ * N_;  // 50176
}

// ---- pre-split operand storage (bf16 hi / lo arrays) -----------------------
__device__ __nv_bfloat16 g_xh[M_ * C_], g_xl[M_ * C_];
__device__ __nv_bfloat16 g_wh[4 * C_ * C_], g_wl[4 * C_ * C_];
__device__ __nv_bfloat16 g_qh[B_ * H_ * N_ * D_], g_ql[B_ * H_ * N_ * D_];
__device__ __nv_bfloat16 g_kh[B_ * H_ * N_ * D_], g_kl[B_ * H_ * N_ * D_];
__device__ __nv_bfloat16 g_vh[B_ * H_ * N_ * D_], g_vl[B_ * H_ * N_ * D_];
__device__ __nv_bfloat16 g_aoh[M_ * C_], g_aol[M_ * C_];
__device__ __nv_bfloat16 g_cph[H_ * N_ * D_], g_cpl[H_ * N_ * D_];
__device__ float g_s[B_ * H_ * N_ * N_];
__device__ __nv_bfloat16 g_sh[B_ * H_ * N_ * N_];
__device__ __nv_bfloat16 g_sl[B_ * H_ * N_ * N_];

// ---- helpers ---------------------------------------------------------------
__device__ __forceinline__ void split_bf(float f, unsigned short& h,
                                         unsigned short& l) {
    __nv_bfloat16 hb = __float2bfloat16(f);
    h = __bfloat16_as_ushort(hb);
    l = __bfloat16_as_ushort(__float2bfloat16(f - __bfloat162float(hb)));
}
__device__ __forceinline__ void split_pack(float a, float b, unsigned& H,
                                           unsigned& L) {
    unsigned short ha, la, hb, lb;
    split_bf(a, ha, la);
    split_bf(b, hb, lb);
    H = (unsigned)ha | ((unsigned)hb << 16);
    L = (unsigned)la | ((unsigned)lb << 16);
}

__device__ __forceinline__ void mma_bf16(float c[4], const unsigned a[4],
                                         const unsigned b[2]) {
    asm volatile(
        "mma.sync.aligned.m16n8k16.row.col.f32.bf16.bf16.f32 "
        "{%0,%1,%2,%3},{%4,%5,%6,%7},{%8,%9},{%0,%1,%2,%3};"
        : "+f"(c[0]), "+f"(c[1]), "+f"(c[2]), "+f"(c[3])
        : "r"(a[0]), "r"(a[1]), "r"(a[2]), "r"(a[3]), "r"(b[0]), "r"(b[1]));
}
__device__ __forceinline__ void mma3(float c[4], const unsigned ah[4],
                                     const unsigned al[4], const unsigned bh[2],
                                     const unsigned bl[2]) {
    mma_bf16(c, ah, bl);
    mma_bf16(c, al, bh);
    mma_bf16(c, ah, bh);
}

__device__ __forceinline__ void cpa16u(uint32_t dst, const void* src) {
    asm volatile("cp.async.cg.shared.global [%0], [%1], 16;"
                 :: "r"(dst), "l"(src));
}
#define CP_COMMIT() asm volatile("cp.async.commit_group;" ::: "memory")
#define CP_WAIT(n)  asm volatile("cp.async.wait_group %0;" :: "n"(n) : "memory")

// ---------------------------------------------------------------------------
__global__ void split_arr(const float* __restrict__ src, int dst_sel, int n4) {
    const int i = blockIdx.x * blockDim.x + threadIdx.x;
    if (i >= n4) return;
    __nv_bfloat16 *dh, *dl;
    if (dst_sel == 0) { dh = g_xh; dl = g_xl; }
    else {
        dh = g_wh + (size_t)(dst_sel - 1) * C_ * C_;
        dl = g_wl + (size_t)(dst_sel - 1) * C_ * C_;
    }
    const float4 v = reinterpret_cast<const float4*>(src)[i];
    unsigned H0, L0, H1, L1;
    split_pack(v.x, v.y, H0, L0);
    split_pack(v.z, v.w, H1, L1);
    reinterpret_cast<uint2*>(dh)[i] = make_uint2(H0, H1);
    reinterpret_cast<uint2*>(dl)[i] = make_uint2(L0, L1);
}

__global__ void build_cp(const float* __restrict__ rel_h,
                         const float* __restrict__ rel_w) {
    const int i = blockIdx.x * blockDim.x + threadIdx.x;
    if (i >= H_ * N_ * D_) return;
    const int t = i % D_;
    const int p = (i / D_) % N_;
    const int h = i / (D_ * N_);
    const float v =
        rel_h[(h * D_ + t) * 14 + p / 14] + rel_w[(h * D_ + t) * 14 + p % 14];
    unsigned short hh, ll;
    split_bf(v, hh, ll);
    g_cph[i] = __ushort_as_bfloat16(hh);
    g_cpl[i] = __ushort_as_bfloat16(ll);
}

// ---------------------------------------------------------------------------
// Projection GEMM (NT).  BM=128, BN=112, BK=16 (49 chunks, exact), 4-stage
// cp.async pipeline.  Stage layout (uints, stride 12/row — conflict-free):
//   Ah @0 [128][12], Al @1536, Bh @3072 [112][12], Bl @4416.  5760 u/stage.
// ---------------------------------------------------------------------------
namespace pj {
constexpr int STAGE_U = 5760;
constexpr int NSTAGE = 4;
constexpr int NCH = C_ / 16;                        // 49, exact
constexpr int SMEM_BYTES = NSTAGE * STAGE_U * 4;    // 92160
}

__device__ __forceinline__ void proj_issue(unsigned* stage, int tid,
                                           const __nv_bfloat16* __restrict__ Ah,
                                           const __nv_bfloat16* __restrict__ Al,
                                           const __nv_bfloat16* __restrict__ Wh,
                                           const __nv_bfloat16* __restrict__ Wl,
                                           int m0, int n0, int k0) {
    // A: 128 rows x 16 k.  thread -> (row = tid/2, arr = tid&1), 16 bf16.
    {
        const int row = tid >> 1, arr = tid & 1;
        const __nv_bfloat16* src =
            (arr ? Al : Ah) + (size_t)(m0 + row) * C_ + k0;
        const uint32_t d = (uint32_t)__cvta_generic_to_shared(
            stage + arr * 1536 + row * 12);
        cpa16u(d, src);
        cpa16u(d + 16, src + 8);
    }
    // W: 112 rows x 16 k.  threads 0..223 -> (row = t/2, arr = t&1).
    if (tid < 224) {
        const int row = tid >> 1, arr = tid & 1;
        const __nv_bfloat16* src =
            (arr ? Wl : Wh) + (size_t)(n0 + row) * C_ + k0;
        const uint32_t d = (uint32_t)__cvta_generic_to_shared(
            stage + 3072 + arr * 1344 + row * 12);
        cpa16u(d, src);
        cpa16u(d + 16, src + 8);
    }
}

__global__ __launch_bounds__(256) void proj_mma2(const float* __restrict__ bias,
                                                 float* __restrict__ out,
                                                 int widx, int sel, int asel) {
    extern __shared__ unsigned sm_u[];

    const __nv_bfloat16* __restrict__ Asrc_h = asel ? g_aoh : g_xh;
    const __nv_bfloat16* __restrict__ Asrc_l = asel ? g_aol : g_xl;
    const __nv_bfloat16* __restrict__ Wh = g_wh + (size_t)widx * C_ * C_;
    const __nv_bfloat16* __restrict__ Wl = g_wl + (size_t)widx * C_ * C_;

    const int tid = threadIdx.x;
    const int wid = tid >> 5, lane = tid & 31;
    const int g = lane >> 2, tig = lane & 3;
    const int wm = wid & 3, wn = wid >> 2;
    const int m0 = blockIdx.y * 128;
    const int n0 = blockIdx.x * 112;

    float c[2][7][4] = {};

    // prologue: fill 3 stages
    proj_issue(sm_u + 0 * pj::STAGE_U, tid, Asrc_h, Asrc_l, Wh, Wl, m0, n0, 0);
    CP_COMMIT();
    proj_issue(sm_u + 1 * pj::STAGE_U, tid, Asrc_h, Asrc_l, Wh, Wl, m0, n0, 16);
    CP_COMMIT();
    proj_issue(sm_u + 2 * pj::STAGE_U, tid, Asrc_h, Asrc_l, Wh, Wl, m0, n0, 32);
    CP_COMMIT();

    for (int ch = 0; ch < pj::NCH; ch++) {
        if (ch < pj::NCH - 2)       CP_WAIT(2);
        else if (ch == pj::NCH - 2) CP_WAIT(1);
        else                        CP_WAIT(0);
        __syncthreads();

        if (ch + 3 < pj::NCH) {
            proj_issue(sm_u + ((ch + 3) & 3) * pj::STAGE_U, tid, Asrc_h,
                       Asrc_l, Wh, Wl, m0, n0, (ch + 3) * 16);
            CP_COMMIT();
        }

        unsigned* stage = sm_u + (ch & 3) * pj::STAGE_U;
        unsigned (*Ahs)[12] = (unsigned(*)[12])(stage);
        unsigned (*Als)[12] = (unsigned(*)[12])(stage + 1536);
        unsigned (*Bhs)[12] = (unsigned(*)[12])(stage + 3072);
        unsigned (*Bls)[12] = (unsigned(*)[12])(stage + 4416);

        unsigned ah[2][4], al[2][4];
#pragma unroll
        for (int mt = 0; mt < 2; mt++) {
            const int rb = wm * 32 + mt * 16;
            ah[mt][0] = Ahs[rb + g][tig];
            ah[mt][1] = Ahs[rb + g + 8][tig];
            ah[mt][2] = Ahs[rb + g][tig + 4];
            ah[mt][3] = Ahs[rb + g + 8][tig + 4];
            al[mt][0] = Als[rb + g][tig];
            al[mt][1] = Als[rb + g + 8][tig];
            al[mt][2] = Als[rb + g][tig + 4];
            al[mt][3] = Als[rb + g + 8][tig + 4];
        }
#pragma unroll
        for (int nt = 0; nt < 7; nt++) {
            const int cb = wn * 56 + nt * 8;
            unsigned bh[2], bl[2];
            bh[0] = Bhs[cb + g][tig];
            bh[1] = Bhs[cb + g][tig + 4];
            bl[0] = Bls[cb + g][tig];
            bl[1] = Bls[cb + g][tig + 4];
#pragma unroll
            for (int mt = 0; mt < 2; mt++)
                mma3(c[mt][nt], ah[mt], al[mt], bh, bl);
        }
    }

    __syncthreads();

#pragma unroll
    for (int mt = 0; mt < 2; mt++) {
#pragma unroll
        for (int nt = 0; nt < 7; nt++) {
#pragma unroll
            for (int eh = 0; eh < 2; eh++) {
                const int row = m0 + wm * 32 + mt * 16 + g + eh * 8;
                const int col0 = n0 + wn * 56 + nt * 8 + 2 * tig;
                const float v0 = c[mt][nt][eh * 2 + 0] + bias[col0];
                const float v1 = c[mt][nt][eh * 2 + 1] + bias[col0 + 1];
                if (sel == 3) {
                    *reinterpret_cast<float2*>(&out[(size_t)row * C_ + col0]) =
                        make_float2(v0, v1);
                } else {
                    unsigned Hp, Lp;
                    split_pack(v0, v1, Hp, Lp);
                    const int bb = row / N_, nn = row % N_;
                    const int hh = col0 / D_, dd = col0 % D_;
                    const size_t off =
                        (((size_t)bb * H_ + hh) * N_ + nn) * D_ + dd;
                    __nv_bfloat16* dh =
                        (sel == 0) ? g_qh : (sel == 1) ? g_kh : g_vh;
                    __nv_bfloat16* dl =
                        (sel == 0) ? g_ql : (sel == 1) ? g_kl : g_vl;
                    *reinterpret_cast<unsigned*>(&dh[off]) = Hp;
                    *reinterpret_cast<unsigned*>(&dl[off]) = Lp;
                }
            }
        }
    }
}

// ---------------------------------------------------------------------------
// Scores: S = (1/14) Q K^T + CP @ Qt.  64x64 tiles; reg-double-buffered;
// one sync/chunk; DEAD-TILE GUARDS (skip mma for padded slabs/octets).
// ---------------------------------------------------------------------------
__global__ __launch_bounds__(256) void scores_mma() {
    __shared__ unsigned Ahs[2][64][12], Als[2][64][12];
    __shared__ unsigned Bhs[2][64][12], Bls[2][64][12];
    __shared__ __nv_bfloat16 B2h[2][64][18], B2l[2][64][18];

    const int bz = blockIdx.z;
    const int h = bz & (H_ - 1);
    const __nv_bfloat16* __restrict__ Qh = g_qh + (size_t)bz * N_ * D_;
    const __nv_bfloat16* __restrict__ Ql = g_ql + (size_t)bz * N_ * D_;
    const __nv_bfloat16* __restrict__ Kh = g_kh + (size_t)bz * N_ * D_;
    const __nv_bfloat16* __restrict__ Kl = g_kl + (size_t)bz * N_ * D_;
    const __nv_bfloat16* __restrict__ CPh = g_cph + (size_t)h * N_ * D_;
    const __nv_bfloat16* __restrict__ CPl = g_cpl + (size_t)h * N_ * D_;

    const int n0 = blockIdx.y * 64;
    const int m0 = blockIdx.x * 64;
    const int tid = threadIdx.x;
    const int wid = tid >> 5, lane = tid & 31;
    const int g = lane >> 2, tig = lane & 3;
    const int wm = wid & 3, wn = wid >> 2;

    const int lr = tid >> 2, lq = (tid & 3) * 4, k2 = (tid & 3) * 2;
    const int lk = tid >> 4, lc = (tid & 15) * 4;

    const bool wvalid = (n0 + wm * 16 < N_);  // warp's 16-row slab has data

    float c[4][4] = {};

    // ======== term 1: Q K^T ========
    uint2 rqh, rql, rkh, rkl;
    {
        rqh = make_uint2(0, 0); rql = make_uint2(0, 0);
        rkh = make_uint2(0, 0); rkl = make_uint2(0, 0);
        if (n0 + lr < N_ && lq + 3 < D_) {
            const size_t e = (size_t)(n0 + lr) * D_ + lq;
            rqh = *reinterpret_cast<const uint2*>(&Qh[e]);
            rql = *reinterpret_cast<const uint2*>(&Ql[e]);
        }
        if (m0 + lr < N_ && lq + 3 < D_) {
            const size_t e = (size_t)(m0 + lr) * D_ + lq;
            rkh = *reinterpret_cast<const uint2*>(&Kh[e]);
            rkl = *reinterpret_cast<const uint2*>(&Kl[e]);
        }
    }
    for (int ci = 0; ci < 13; ci++) {
        const int st = ci & 1;
        *reinterpret_cast<uint2*>(&Ahs[st][lr][k2]) = rqh;
        *reinterpret_cast<uint2*>(&Als[st][lr][k2]) = rql;
        *reinterpret_cast<uint2*>(&Bhs[st][lr][k2]) = rkh;
        *reinterpret_cast<uint2*>(&Bls[st][lr][k2]) = rkl;
        __syncthreads();

        if (ci + 1 < 13) {
            const int k0 = (ci + 1) * 16;
            rqh = make_uint2(0, 0); rql = make_uint2(0, 0);
            rkh = make_uint2(0, 0); rkl = make_uint2(0, 0);
            if (n0 + lr < N_ && k0 + lq + 3 < D_) {
                const size_t e = (size_t)(n0 + lr) * D_ + k0 + lq;
                rqh = *reinterpret_cast<const uint2*>(&Qh[e]);
                rql = *reinterpret_cast<const uint2*>(&Ql[e]);
            }
            if (m0 + lr < N_ && k0 + lq + 3 < D_) {
                const size_t e = (size_t)(m0 + lr) * D_ + k0 + lq;
                rkh = *reinterpret_cast<const uint2*>(&Kh[e]);
                rkl = *reinterpret_cast<const uint2*>(&Kl[e]);
            }
        }

        if (wvalid) {
            unsigned ah[4], al[4];
            const int rb = wm * 16;
            ah[0] = Ahs[st][rb + g][tig];     al[0] = Als[st][rb + g][tig];
            ah[1] = Ahs[st][rb + g + 8][tig]; al[1] = Als[st][rb + g + 8][tig];
            ah[2] = Ahs[st][rb + g][tig + 4]; al[2] = Als[st][rb + g][tig + 4];
            ah[3] = Ahs[st][rb + g + 8][tig + 4];
            al[3] = Als[st][rb + g + 8][tig + 4];
#pragma unroll
            for (int nt = 0; nt < 4; nt++) {
                const int cb = wn * 32 + nt * 8;
                if (m0 + cb >= N_) continue;
                unsigned bh[2], bl[2];
                bh[0] = Bhs[st][cb + g][tig];     bl[0] = Bls[st][cb + g][tig];
                bh[1] = Bhs[st][cb + g][tig + 4]; bl[1] = Bls[st][cb + g][tig + 4];
                mma3(c[nt], ah, al, bh, bl);
            }
        }
    }

    constexpr float scale = 1.0f / 14.0f;
#pragma unroll
    for (int nt = 0; nt < 4; nt++)
#pragma unroll
        for (int e = 0; e < 4; e++) c[nt][e] *= scale;

    __syncthreads();

    // ======== term 2: CP @ Qt ========
    uint2 rch, rcl, rbh, rbl;
    {
        rch = make_uint2(0, 0); rcl = make_uint2(0, 0);
        rbh = make_uint2(0, 0); rbl = make_uint2(0, 0);
        if (n0 + lr < N_ && lq + 3 < D_) {
            const size_t e = (size_t)(n0 + lr) * D_ + lq;
            rch = *reinterpret_cast<const uint2*>(&CPh[e]);
            rcl = *reinterpret_cast<const uint2*>(&CPl[e]);
        }
        if (lk < N_ && m0 + lc + 3 < D_) {
            const size_t e = (size_t)lk * D_ + m0 + lc;
            rbh = *reinterpret_cast<const uint2*>(&Qh[e]);
            rbl = *reinterpret_cast<const uint2*>(&Ql[e]);
        }
    }
    for (int ci = 0; ci < 13; ci++) {
        const int st = ci & 1;
        *reinterpret_cast<uint2*>(&Ahs[st][lr][k2]) = rch;
        *reinterpret_cast<uint2*>(&Als[st][lr][k2]) = rcl;
        {
            const __nv_bfloat16* ph = reinterpret_cast<const __nv_bfloat16*>(&rbh);
            const __nv_bfloat16* pl = reinterpret_cast<const __nv_bfloat16*>(&rbl);
#pragma unroll
            for (int j = 0; j < 4; j++) {
                B2h[st][lc + j][lk] = ph[j];
                B2l[st][lc + j][lk] = pl[j];
            }
        }
        __syncthreads();

        if (ci + 1 < 13) {
            const int k0 = (ci + 1) * 16;
            rch = make_uint2(0, 0); rcl = make_uint2(0, 0);
            rbh = make_uint2(0, 0); rbl = make_uint2(0, 0);
            if (n0 + lr < N_ && k0 + lq + 3 < D_) {
                const size_t e = (size_t)(n0 + lr) * D_ + k0 + lq;
                rch = *reinterpret_cast<const uint2*>(&CPh[e]);
                rcl = *reinterpret_cast<const uint2*>(&CPl[e]);
            }
            if (k0 + lk < N_ && m0 + lc + 3 < D_) {
                const size_t e = (size_t)(k0 + lk) * D_ + m0 + lc;
                rbh = *reinterpret_cast<const uint2*>(&Qh[e]);
                rbl = *reinterpret_cast<const uint2*>(&Ql[e]);
            }
        }

        if (wvalid) {
            unsigned ah[4], al[4];
            const int rb = wm * 16;
            ah[0] = Ahs[st][rb + g][tig];     al[0] = Als[st][rb + g][tig];
            ah[1] = Ahs[st][rb + g + 8][tig]; al[1] = Als[st][rb + g + 8][tig];
            ah[2] = Ahs[st][rb + g][tig + 4]; al[2] = Als[st][rb + g][tig + 4];
            ah[3] = Ahs[st][rb + g + 8][tig + 4];
            al[3] = Als[st][rb + g + 8][tig + 4];
#pragma unroll
            for (int nt = 0; nt < 4; nt++) {
                const int cb = wn * 32 + nt * 8;
                if (m0 + cb >= N_) continue;
                unsigned bh[2], bl[2];
                bh[0] = *reinterpret_cast<const unsigned*>(&B2h[st][cb + g][2 * tig]);
                bh[1] = *reinterpret_cast<const unsigned*>(&B2h[st][cb + g][2 * tig + 8]);
                bl[0] = *reinterpret_cast<const unsigned*>(&B2l[st][cb + g][2 * tig]);
                bl[1] = *reinterpret_cast<const unsigned*>(&B2l[st][cb + g][2 * tig + 8]);
                mma3(c[nt], ah, al, bh, bl);
            }
        }
    }

    float* __restrict__ S = g_s + (size_t)bz * N_ * N_;
#pragma unroll
    for (int nt = 0; nt < 4; nt++) {
#pragma unroll
        for (int eh = 0; eh < 2; eh++) {
            const int n = n0 + wm * 16 + g + eh * 8;
            const int m = m0 + wn * 32 + nt * 8 + 2 * tig;
            if (n < N_ && m < N_)
                *reinterpret_cast<float2*>(&S[(size_t)n * N_ + m]) =
                    make_float2(c[nt][eh * 2], c[nt][eh * 2 + 1]);
        }
    }
}

// ---------------------------------------------------------------------------
__global__ __launch_bounds__(256) void softmax_kernel() {
    const int w = blockIdx.x * 8 + (threadIdx.x >> 5);
    const int lane = threadIdx.x & 31;
    if (w >= B_ * H_ * N_) return;
    const float* __restrict__ row = g_s + (size_t)w * N_;
    __nv_bfloat16* __restrict__ rh = g_sh + (size_t)w * N_;
    __nv_bfloat16* __restrict__ rl = g_sl + (size_t)w * N_;

    float v[7];
    float mx = -3.4e38f;
#pragma unroll
    for (int i = 0; i < 7; i++) {
        const int cc = lane + i * 32;
        v[i] = (cc < N_) ? row[cc] : -3.4e38f;
        mx = fmaxf(mx, v[i]);
    }
#pragma unroll
    for (int o = 16; o; o >>= 1) mx = fmaxf(mx, __shfl_xor_sync(0xffffffffu, mx, o));
    float s = 0.f;
#pragma unroll
    for (int i = 0; i < 7; i++) {
        const int cc = lane + i * 32;
        v[i] = (cc < N_) ? __expf(v[i] - mx) : 0.f;
        s += v[i];
    }
#pragma unroll
    for (int o = 16; o; o >>= 1) s += __shfl_xor_sync(0xffffffffu, s, o);
    const float inv = 1.0f / s;
#pragma unroll
    for (int i = 0; i < 7; i++) {
        const int cc = lane + i * 32;
        if (cc < N_) {
            unsigned short hh, ll;
            split_bf(v[i] * inv, hh, ll);
            rh[cc] = __ushort_as_bfloat16(hh);
            rl[cc] = __ushort_as_bfloat16(ll);
        }
    }
}

// ---------------------------------------------------------------------------
// O = A @ V with dead-tile guards; A/V pre-split; split store to ao.
// ---------------------------------------------------------------------------
__global__ __launch_bounds__(256) void av_mma() {
    __shared__ unsigned Ahs[2][64][12], Als[2][64][12];
    __shared__ __nv_bfloat16 B2h[2][64][18], B2l[2][64][18];

    const int bz = blockIdx.z;
    const int b = bz >> 2, h = bz & 3;
    const __nv_bfloat16* __restrict__ Ph = g_sh + (size_t)bz * N_ * N_;
    const __nv_bfloat16* __restrict__ Pl = g_sl + (size_t)bz * N_ * N_;
    const __nv_bfloat16* __restrict__ Vh = g_vh + (size_t)bz * N_ * D_;
    const __nv_bfloat16* __restrict__ Vl = g_vl + (size_t)bz * N_ * D_;

    const int n0 = blockIdx.y * 64;
    const int d0 = blockIdx.x * 64;
    const int tid = threadIdx.x;
    const int wid = tid >> 5, lane = tid & 31;
    const int g = lane >> 2, tig = lane & 3;
    const int wm = wid & 3, wn = wid >> 2;

    const int lr = tid >> 2, lq = (tid & 3) * 4, k2 = (tid & 3) * 2;
    const int lk = tid >> 4, lc = (tid & 15) * 4;

    const bool wvalid = (n0 + wm * 16 < N_);

    float c[4][4] = {};

    uint2 rah, ral, rbh, rbl;
    {
        rah = make_uint2(0, 0); ral = make_uint2(0, 0);
        rbh = make_uint2(0, 0); rbl = make_uint2(0, 0);
        if (n0 + lr < N_ && lq + 3 < N_) {
            const size_t e = (size_t)(n0 + lr) * N_ + lq;
            rah = *reinterpret_cast<const uint2*>(&Ph[e]);
            ral = *reinterpret_cast<const uint2*>(&Pl[e]);
        }
        if (lk < N_ && d0 + lc + 3 < D_) {
            const size_t e = (size_t)lk * D_ + d0 + lc;
            rbh = *reinterpret_cast<const uint2*>(&Vh[e]);
            rbl = *reinterpret_cast<const uint2*>(&Vl[e]);
        }
    }
    for (int ci = 0; ci < 13; ci++) {
        const int st = ci & 1;
        *reinterpret_cast<uint2*>(&Ahs[st][lr][k2]) = rah;
        *reinterpret_cast<uint2*>(&Als[st][lr][k2]) = ral;
        {
            const __nv_bfloat16* ph = reinterpret_cast<const __nv_bfloat16*>(&rbh);
            const __nv_bfloat16* pl = reinterpret_cast<const __nv_bfloat16*>(&rbl);
#pragma unroll
            for (int j = 0; j < 4; j++) {
                B2h[st][lc + j][lk] = ph[j];
                B2l[st][lc + j][lk] = pl[j];
            }
        }
        __syncthreads();

        if (ci + 1 < 13) {
            const int k0 = (ci + 1) * 16;
            rah = make_uint2(0, 0); ral = make_uint2(0, 0);
            rbh = make_uint2(0, 0); rbl = make_uint2(0, 0);
            if (n0 + lr < N_ && k0 + lq + 3 < N_) {
                const size_t e = (size_t)(n0 + lr) * N_ + k0 + lq;
                rah = *reinterpret_cast<const uint2*>(&Ph[e]);
                ral = *reinterpret_cast<const uint2*>(&Pl[e]);
            }
            if (k0 + lk < N_ && d0 + lc + 3 < D_) {
                const size_t e = (size_t)(k0 + lk) * D_ + d0 + lc;
                rbh = *reinterpret_cast<const uint2*>(&Vh[e]);
                rbl = *reinterpret_cast<const uint2*>(&Vl[e]);
            }
        }

        if (wvalid) {
            unsigned ah[4], al[4];
            const int rb = wm * 16;
            ah[0] = Ahs[st][rb + g][tig];     al[0] = Als[st][rb + g][tig];
            ah[1] = Ahs[st][rb + g + 8][tig]; al[1] = Als[st][rb + g + 8][tig];
            ah[2] = Ahs[st][rb + g][tig + 4]; al[2] = Als[st][rb + g][tig + 4];
            ah[3] = Ahs[st][rb + g + 8][tig + 4];
            al[3] = Als[st][rb + g + 8][tig + 4];
#pragma unroll
            for (int nt = 0; nt < 4; nt++) {
                const int cb = wn * 32 + nt * 8;
                if (d0 + cb >= D_) continue;
                unsigned bh[2], bl[2];
                bh[0] = *reinterpret_cast<const unsigned*>(&B2h[st][cb + g][2 * tig]);
                bh[1] = *reinterpret_cast<const unsigned*>(&B2h[st][cb + g][2 * tig + 8]);
                bl[0] = *reinterpret_cast<const unsigned*>(&B2l[st][cb + g][2 * tig]);
                bl[1] = *reinterpret_cast<const unsigned*>(&B2l[st][cb + g][2 * tig + 8]);
                mma3(c[nt], ah, al, bh, bl);
            }
        }
    }

#pragma unroll
    for (int nt = 0; nt < 4; nt++) {
#pragma unroll
        for (int eh = 0; eh < 2; eh++) {
            const int n = n0 + wm * 16 + g + eh * 8;
            const int d = d0 + wn * 32 + nt * 8 + 2 * tig;
            if (n < N_ && d < D_) {
                unsigned Hp, Lp;
                split_pack(c[nt][eh * 2], c[nt][eh * 2 + 1], Hp, Lp);
                const size_t off = ((size_t)b * N_ + n) * C_ + h * D_ + d;
                *reinterpret_cast<unsigned*>(&g_aoh[off]) = Hp;
                *reinterpret_cast<unsigned*>(&g_aol[off]) = Lp;
            }
        }
    }
}

// ---------------------------------------------------------------------------
extern "C" void kernel_launch(void* const* d_in, const int* in_sizes, int n_in,
                              void* d_out, int out_size) {
    const float* x  = (const float*)d_in[0];
    const float* Wq = (const float*)d_in[1];
    const float* bq = (const float*)d_in[2];
    const float* Wk = (const float*)d_in[3];
    const float* bk = (const float*)d_in[4];
    const float* Wv = (const float*)d_in[5];
    const float* bv = (const float*)d_in[6];
    const float* Wo = (const float*)d_in[7];
    const float* bo = (const float*)d_in[8];
    const float* rh = (const float*)d_in[9];
    const float* rw = (const float*)d_in[10];
    float* out = (float*)d_out;

    cudaFuncSetAttribute(proj_mma2, cudaFuncAttributeMaxDynamicSharedMemorySize,
                         pj::SMEM_BYTES);

    const int n4x = M_ * C_ / 4;
    const int n4w = C_ * C_ / 4;
    split_arr<<<(n4x + 255) / 256, 256>>>(x, 0, n4x);
    split_arr<<<(n4w + 255) / 256, 256>>>(Wq, 1, n4w);
    split_arr<<<(n4w + 255) / 256, 256>>>(Wk, 2, n4w);
    split_arr<<<(n4w + 255) / 256, 256>>>(Wv, 3, n4w);
    split_arr<<<(n4w + 255) / 256, 256>>>(Wo, 4, n4w);

    build_cp<<<(H_ * N_ * D_ + 255) / 256, 256>>>(rh, rw);

    dim3 gproj(C_ / 112, M_ / 128);  // (7, 392)
    proj_mma2<<<gproj, 256, pj::SMEM_BYTES>>>(bq, nullptr, 0, 0, 0);
    proj_mma2<<<gproj, 256, pj::SMEM_BYTES>>>(bk, nullptr, 1, 1, 0);
    proj_mma2<<<gproj, 256, pj::SMEM_BYTES>>>(bv, nullptr, 2, 2, 0);

    dim3 gatt(4, 4, B_ * H_);
    scores_mma<<<gatt, 256>>>();
    softmax_kernel<<<(B_ * H_ * N_ + 7) / 8, 256>>>();
    av_mma<<<gatt, 256>>>();

    proj_mma2<<<gproj, 256, pj::SMEM_BYTES>>>(bo, out, 3, 3, 1);
}

// round 13
// speedup vs baseline: 1.1186x; 1.1186x over previous
#include <cuda_runtime.h>
#include <cuda_bf16.h>
#include <cstdint>

// MHSA with RPE bias.  B=256, N=196, C=784, H=4, D=196.
// Round 13: R11 (BK=32 2-stage cp.async proj, reg-double-buffered attention,
// pre-split probs) + attention dead-tile guards ONLY (single-variable change
// vs R11; the R12 BK=16 proj rebuild is reverted — it regressed).

namespace {
constexpr int B_ = 256, N_ = 196, C_ = 784, H_ = 4, D_ = 196;
constexpr int M_ = B_ * N_;  // 50176
}

// ---- pre-split operand storage (bf16 hi / lo arrays) -----------------------
__device__ __nv_bfloat16 g_xh[M_ * C_], g_xl[M_ * C_];
__device__ __nv_bfloat16 g_wh[4 * C_ * C_], g_wl[4 * C_ * C_];
__device__ __nv_bfloat16 g_qh[B_ * H_ * N_ * D_], g_ql[B_ * H_ * N_ * D_];
__device__ __nv_bfloat16 g_kh[B_ * H_ * N_ * D_], g_kl[B_ * H_ * N_ * D_];
__device__ __nv_bfloat16 g_vh[B_ * H_ * N_ * D_], g_vl[B_ * H_ * N_ * D_];
__device__ __nv_bfloat16 g_aoh[M_ * C_], g_aol[M_ * C_];
__device__ __nv_bfloat16 g_cph[H_ * N_ * D_], g_cpl[H_ * N_ * D_];
__device__ float g_s[B_ * H_ * N_ * N_];
__device__ __nv_bfloat16 g_sh[B_ * H_ * N_ * N_];
__device__ __nv_bfloat16 g_sl[B_ * H_ * N_ * N_];

// ---- helpers ---------------------------------------------------------------
__device__ __forceinline__ void split_bf(float f, unsigned short& h,
                                         unsigned short& l) {
    __nv_bfloat16 hb = __float2bfloat16(f);
    h = __bfloat16_as_ushort(hb);
    l = __bfloat16_as_ushort(__float2bfloat16(f - __bfloat162float(hb)));
}
__device__ __forceinline__ void split_pack(float a, float b, unsigned& H,
                                           unsigned& L) {
    unsigned short ha, la, hb, lb;
    split_bf(a, ha, la);
    split_bf(b, hb, lb);
    H = (unsigned)ha | ((unsigned)hb << 16);
    L = (unsigned)la | ((unsigned)lb << 16);
}

__device__ __forceinline__ void mma_bf16(float c[4], const unsigned a[4],
                                         const unsigned b[2]) {
    asm volatile(
        "mma.sync.aligned.m16n8k16.row.col.f32.bf16.bf16.f32 "
        "{%0,%1,%2,%3},{%4,%5,%6,%7},{%8,%9},{%0,%1,%2,%3};"
        : "+f"(c[0]), "+f"(c[1]), "+f"(c[2]), "+f"(c[3])
        : "r"(a[0]), "r"(a[1]), "r"(a[2]), "r"(a[3]), "r"(b[0]), "r"(b[1]));
}
__device__ __forceinline__ void mma3(float c[4], const unsigned ah[4],
                                     const unsigned al[4], const unsigned bh[2],
                                     const unsigned bl[2]) {
    mma_bf16(c, ah, bl);
    mma_bf16(c, al, bh);
    mma_bf16(c, ah, bh);
}

__device__ __forceinline__ void cpa16(uint32_t dst, const void* src, bool p) {
    const int sz = p ? 16 : 0;
    asm volatile("cp.async.cg.shared.global [%0], [%1], 16, %2;"
                 :: "r"(dst), "l"(src), "r"(sz));
}
#define CP_COMMIT() asm volatile("cp.async.commit_group;" ::: "memory")
#define CP_WAIT(n)  asm volatile("cp.async.wait_group %0;" :: "n"(n) : "memory")

// ---------------------------------------------------------------------------
__global__ void split_arr(const float* __restrict__ src, int dst_sel, int n4) {
    const int i = blockIdx.x * blockDim.x + threadIdx.x;
    if (i >= n4) return;
    __nv_bfloat16 *dh, *dl;
    if (dst_sel == 0) { dh = g_xh; dl = g_xl; }
    else {
        dh = g_wh + (size_t)(dst_sel - 1) * C_ * C_;
        dl = g_wl + (size_t)(dst_sel - 1) * C_ * C_;
    }
    const float4 v = reinterpret_cast<const float4*>(src)[i];
    unsigned H0, L0, H1, L1;
    split_pack(v.x, v.y, H0, L0);
    split_pack(v.z, v.w, H1, L1);
    reinterpret_cast<uint2*>(dh)[i] = make_uint2(H0, H1);
    reinterpret_cast<uint2*>(dl)[i] = make_uint2(L0, L1);
}

__global__ void build_cp(const float* __restrict__ rel_h,
                         const float* __restrict__ rel_w) {
    const int i = blockIdx.x * blockDim.x + threadIdx.x;
    if (i >= H_ * N_ * D_) return;
    const int t = i % D_;
    const int p = (i / D_) % N_;
    const int h = i / (D_ * N_);
    const float v =
        rel_h[(h * D_ + t) * 14 + p / 14] + rel_w[(h * D_ + t) * 14 + p % 14];
    unsigned short hh, ll;
    split_bf(v, hh, ll);
    g_cph[i] = __ushort_as_bfloat16(hh);
    g_cpl[i] = __ushort_as_bfloat16(ll);
}

// ---------------------------------------------------------------------------
// Projection GEMM (exact R10/R11 form: BK=32, 2-stage cp.async ping-pong).
// ---------------------------------------------------------------------------
namespace pj {
constexpr int STAGE_U = 9600;
constexpr int NCH = (C_ + 31) / 32;           // 25
constexpr int SMEM_BYTES = 2 * STAGE_U * 4;   // 76800
}

__device__ __forceinline__ void proj_issue(unsigned* stage, int tid,
                                           const __nv_bfloat16* __restrict__ Ah,
                                           const __nv_bfloat16* __restrict__ Al,
                                           const __nv_bfloat16* __restrict__ Wh,
                                           const __nv_bfloat16* __restrict__ Wl,
                                           int m0, int n0, int k0) {
    {
        const int row = tid >> 1, half = tid & 1;
        const int kk = k0 + half * 16;
        const bool ok = (kk + 15 < C_);
        const size_t e0 = (size_t)(m0 + row) * C_ + kk;
        const uint32_t dh =
            (uint32_t)__cvta_generic_to_shared(stage + row * 20 + half * 8);
        cpa16(dh, Ah + e0, ok);
        cpa16(dh + 16, Ah + e0 + 8, ok);
        const uint32_t dl = (uint32_t)__cvta_generic_to_shared(
            stage + 2560 + row * 20 + half * 8);
        cpa16(dl, Al + e0, ok);
        cpa16(dl + 16, Al + e0 + 8, ok);
    }
    for (int u = tid; u < 112 * 4; u += 256) {
        const int wr = u >> 2, q = u & 3;
        const int kk = k0 + q * 8;
        const bool ok = (kk + 7 < C_);
        const size_t e0 = (size_t)(n0 + wr) * C_ + kk;
        const uint32_t dh =
            (uint32_t)__cvta_generic_to_shared(stage + 5120 + wr * 20 + q * 4);
        cpa16(dh, Wh + e0, ok);
        const uint32_t dl =
            (uint32_t)__cvta_generic_to_shared(stage + 7360 + wr * 20 + q * 4);
        cpa16(dl, Wl + e0, ok);
    }
}

__global__ __launch_bounds__(256) void proj_mma2(const float* __restrict__ bias,
                                                 float* __restrict__ out,
                                                 int widx, int sel, int asel) {
    extern __shared__ unsigned sm_u[];

    const __nv_bfloat16* __restrict__ Asrc_h = asel ? g_aoh : g_xh;
    const __nv_bfloat16* __restrict__ Asrc_l = asel ? g_aol : g_xl;
    const __nv_bfloat16* __restrict__ Wh = g_wh + (size_t)widx * C_ * C_;
    const __nv_bfloat16* __restrict__ Wl = g_wl + (size_t)widx * C_ * C_;

    const int tid = threadIdx.x;
    const int wid = tid >> 5, lane = tid & 31;
    const int g = lane >> 2, tig = lane & 3;
    const int wm = wid & 3, wn = wid >> 2;
    const int m0 = blockIdx.y * 128;
    const int n0 = blockIdx.x * 112;

    float c[2][7][4] = {};

    proj_issue(sm_u, tid, Asrc_h, Asrc_l, Wh, Wl, m0, n0, 0);
    CP_COMMIT();

    for (int ch = 0; ch < pj::NCH; ch++) {
        if (ch + 1 < pj::NCH) {
            proj_issue(sm_u + ((ch + 1) & 1) * pj::STAGE_U, tid, Asrc_h,
                       Asrc_l, Wh, Wl, m0, n0, (ch + 1) * 32);
            CP_COMMIT();
            CP_WAIT(1);
        } else {
            CP_WAIT(0);
        }
        __syncthreads();

        unsigned* stage = sm_u + (ch & 1) * pj::STAGE_U;
        unsigned (*Ahs)[20] = (unsigned(*)[20])(stage);
        unsigned (*Als)[20] = (unsigned(*)[20])(stage + 2560);
        unsigned (*Bhs)[20] = (unsigned(*)[20])(stage + 5120);
        unsigned (*Bls)[20] = (unsigned(*)[20])(stage + 7360);

#pragma unroll
        for (int ks = 0; ks < 2; ks++) {
            const int kb = ks * 8;
            unsigned ah[2][4], al[2][4];
#pragma unroll
            for (int mt = 0; mt < 2; mt++) {
                const int rb = wm * 32 + mt * 16;
                ah[mt][0] = Ahs[rb + g][kb + tig];
                ah[mt][1] = Ahs[rb + g + 8][kb + tig];
                ah[mt][2] = Ahs[rb + g][kb + tig + 4];
                ah[mt][3] = Ahs[rb + g + 8][kb + tig + 4];
                al[mt][0] = Als[rb + g][kb + tig];
                al[mt][1] = Als[rb + g + 8][kb + tig];
                al[mt][2] = Als[rb + g][kb + tig + 4];
                al[mt][3] = Als[rb + g + 8][kb + tig + 4];
            }
#pragma unroll
            for (int nt = 0; nt < 7; nt++) {
                const int cb = wn * 56 + nt * 8;
                unsigned bh[2], bl[2];
                bh[0] = Bhs[cb + g][kb + tig];
                bh[1] = Bhs[cb + g][kb + tig + 4];
                bl[0] = Bls[cb + g][kb + tig];
                bl[1] = Bls[cb + g][kb + tig + 4];
#pragma unroll
                for (int mt = 0; mt < 2; mt++)
                    mma3(c[mt][nt], ah[mt], al[mt], bh, bl);
            }
        }
        __syncthreads();
    }

#pragma unroll
    for (int mt = 0; mt < 2; mt++) {
#pragma unroll
        for (int nt = 0; nt < 7; nt++) {
#pragma unroll
            for (int eh = 0; eh < 2; eh++) {
                const int row = m0 + wm * 32 + mt * 16 + g + eh * 8;
                const int col0 = n0 + wn * 56 + nt * 8 + 2 * tig;
                const float v0 = c[mt][nt][eh * 2 + 0] + bias[col0];
                const float v1 = c[mt][nt][eh * 2 + 1] + bias[col0 + 1];
                if (sel == 3) {
                    *reinterpret_cast<float2*>(&out[(size_t)row * C_ + col0]) =
                        make_float2(v0, v1);
                } else {
                    unsigned Hp, Lp;
                    split_pack(v0, v1, Hp, Lp);
                    const int bb = row / N_, nn = row % N_;
                    const int hh = col0 / D_, dd = col0 % D_;
                    const size_t off =
                        (((size_t)bb * H_ + hh) * N_ + nn) * D_ + dd;
                    __nv_bfloat16* dh =
                        (sel == 0) ? g_qh : (sel == 1) ? g_kh : g_vh;
                    __nv_bfloat16* dl =
                        (sel == 0) ? g_ql : (sel == 1) ? g_kl : g_vl;
                    *reinterpret_cast<unsigned*>(&dh[off]) = Hp;
                    *reinterpret_cast<unsigned*>(&dl[off]) = Lp;
                }
            }
        }
    }
}

// ---------------------------------------------------------------------------
// Scores (R11 + dead-tile guards).
// ---------------------------------------------------------------------------
__global__ __launch_bounds__(256) void scores_mma() {
    __shared__ unsigned Ahs[2][64][12], Als[2][64][12];
    __shared__ unsigned Bhs[2][64][12], Bls[2][64][12];
    __shared__ __nv_bfloat16 B2h[2][64][18], B2l[2][64][18];

    const int bz = blockIdx.z;
    const int h = bz & (H_ - 1);
    const __nv_bfloat16* __restrict__ Qh = g_qh + (size_t)bz * N_ * D_;
    const __nv_bfloat16* __restrict__ Ql = g_ql + (size_t)bz * N_ * D_;
    const __nv_bfloat16* __restrict__ Kh = g_kh + (size_t)bz * N_ * D_;
    const __nv_bfloat16* __restrict__ Kl = g_kl + (size_t)bz * N_ * D_;
    const __nv_bfloat16* __restrict__ CPh = g_cph + (size_t)h * N_ * D_;
    const __nv_bfloat16* __restrict__ CPl = g_cpl + (size_t)h * N_ * D_;

    const int n0 = blockIdx.y * 64;
    const int m0 = blockIdx.x * 64;
    const int tid = threadIdx.x;
    const int wid = tid >> 5, lane = tid & 31;
    const int g = lane >> 2, tig = lane & 3;
    const int wm = wid & 3, wn = wid >> 2;

    const int lr = tid >> 2, lq = (tid & 3) * 4, k2 = (tid & 3) * 2;
    const int lk = tid >> 4, lc = (tid & 15) * 4;

    const bool wvalid = (n0 + wm * 16 < N_);

    float c[4][4] = {};

    // ======== term 1: Q K^T ========
    uint2 rqh, rql, rkh, rkl;
    {
        rqh = make_uint2(0, 0); rql = make_uint2(0, 0);
        rkh = make_uint2(0, 0); rkl = make_uint2(0, 0);
        if (n0 + lr < N_ && lq + 3 < D_) {
            const size_t e = (size_t)(n0 + lr) * D_ + lq;
            rqh = *reinterpret_cast<const uint2*>(&Qh[e]);
            rql = *reinterpret_cast<const uint2*>(&Ql[e]);
        }
        if (m0 + lr < N_ && lq + 3 < D_) {
            const size_t e = (size_t)(m0 + lr) * D_ + lq;
            rkh = *reinterpret_cast<const uint2*>(&Kh[e]);
            rkl = *reinterpret_cast<const uint2*>(&Kl[e]);
        }
    }
    for (int ci = 0; ci < 13; ci++) {
        const int st = ci & 1;
        *reinterpret_cast<uint2*>(&Ahs[st][lr][k2]) = rqh;
        *reinterpret_cast<uint2*>(&Als[st][lr][k2]) = rql;
        *reinterpret_cast<uint2*>(&Bhs[st][lr][k2]) = rkh;
        *reinterpret_cast<uint2*>(&Bls[st][lr][k2]) = rkl;
        __syncthreads();

        if (ci + 1 < 13) {
            const int k0 = (ci + 1) * 16;
            rqh = make_uint2(0, 0); rql = make_uint2(0, 0);
            rkh = make_uint2(0, 0); rkl = make_uint2(0, 0);
            if (n0 + lr < N_ && k0 + lq + 3 < D_) {
                const size_t e = (size_t)(n0 + lr) * D_ + k0 + lq;
                rqh = *reinterpret_cast<const uint2*>(&Qh[e]);
                rql = *reinterpret_cast<const uint2*>(&Ql[e]);
            }
            if (m0 + lr < N_ && k0 + lq + 3 < D_) {
                const size_t e = (size_t)(m0 + lr) * D_ + k0 + lq;
                rkh = *reinterpret_cast<const uint2*>(&Kh[e]);
                rkl = *reinterpret_cast<const uint2*>(&Kl[e]);
            }
        }

        if (wvalid) {
            unsigned ah[4], al[4];
            const int rb = wm * 16;
            ah[0] = Ahs[st][rb + g][tig];     al[0] = Als[st][rb + g][tig];
            ah[1] = Ahs[st][rb + g + 8][tig]; al[1] = Als[st][rb + g + 8][tig];
            ah[2] = Ahs[st][rb + g][tig + 4]; al[2] = Als[st][rb + g][tig + 4];
            ah[3] = Ahs[st][rb + g + 8][tig + 4];
            al[3] = Als[st][rb + g + 8][tig + 4];
#pragma unroll
            for (int nt = 0; nt < 4; nt++) {
                const int cb = wn * 32 + nt * 8;
                if (m0 + cb >= N_) continue;
                unsigned bh[2], bl[2];
                bh[0] = Bhs[st][cb + g][tig];     bl[0] = Bls[st][cb + g][tig];
                bh[1] = Bhs[st][cb + g][tig + 4]; bl[1] = Bls[st][cb + g][tig + 4];
                mma3(c[nt], ah, al, bh, bl);
            }
        }
    }

    constexpr float scale = 1.0f / 14.0f;
#pragma unroll
    for (int nt = 0; nt < 4; nt++)
#pragma unroll
        for (int e = 0; e < 4; e++) c[nt][e] *= scale;

    __syncthreads();

    // ======== term 2: CP @ Qt ========
    uint2 rch, rcl, rbh, rbl;
    {
        rch = make_uint2(0, 0); rcl = make_uint2(0, 0);
        rbh = make_uint2(0, 0); rbl = make_uint2(0, 0);
        if (n0 + lr < N_ && lq + 3 < D_) {
            const size_t e = (size_t)(n0 + lr) * D_ + lq;
            rch = *reinterpret_cast<const uint2*>(&CPh[e]);
            rcl = *reinterpret_cast<const uint2*>(&CPl[e]);
        }
        if (lk < N_ && m0 + lc + 3 < D_) {
            const size_t e = (size_t)lk * D_ + m0 + lc;
            rbh = *reinterpret_cast<const uint2*>(&Qh[e]);
            rbl = *reinterpret_cast<const uint2*>(&Ql[e]);
        }
    }
    for (int ci = 0; ci < 13; ci++) {
        const int st = ci & 1;
        *reinterpret_cast<uint2*>(&Ahs[st][lr][k2]) = rch;
        *reinterpret_cast<uint2*>(&Als[st][lr][k2]) = rcl;
        {
            const __nv_bfloat16* ph = reinterpret_cast<const __nv_bfloat16*>(&rbh);
            const __nv_bfloat16* pl = reinterpret_cast<const __nv_bfloat16*>(&rbl);
#pragma unroll
            for (int j = 0; j < 4; j++) {
                B2h[st][lc + j][lk] = ph[j];
                B2l[st][lc + j][lk] = pl[j];
            }
        }
        __syncthreads();

        if (ci + 1 < 13) {
            const int k0 = (ci + 1) * 16;
            rch = make_uint2(0, 0); rcl = make_uint2(0, 0);
            rbh = make_uint2(0, 0); rbl = make_uint2(0, 0);
            if (n0 + lr < N_ && k0 + lq + 3 < D_) {
                const size_t e = (size_t)(n0 + lr) * D_ + k0 + lq;
                rch = *reinterpret_cast<const uint2*>(&CPh[e]);
                rcl = *reinterpret_cast<const uint2*>(&CPl[e]);
            }
            if (k0 + lk < N_ && m0 + lc + 3 < D_) {
                const size_t e = (size_t)(k0 + lk) * D_ + m0 + lc;
                rbh = *reinterpret_cast<const uint2*>(&Qh[e]);
                rbl = *reinterpret_cast<const uint2*>(&Ql[e]);
            }
        }

        if (wvalid) {
            unsigned ah[4], al[4];
            const int rb = wm * 16;
            ah[0] = Ahs[st][rb + g][tig];     al[0] = Als[st][rb + g][tig];
            ah[1] = Ahs[st][rb + g + 8][tig]; al[1] = Als[st][rb + g + 8][tig];
            ah[2] = Ahs[st][rb + g][tig + 4]; al[2] = Als[st][rb + g][tig + 4];
            ah[3] = Ahs[st][rb + g + 8][tig + 4];
            al[3] = Als[st][rb + g + 8][tig + 4];
#pragma unroll
            for (int nt = 0; nt < 4; nt++) {
                const int cb = wn * 32 + nt * 8;
                if (m0 + cb >= N_) continue;
                unsigned bh[2], bl[2];
                bh[0] = *reinterpret_cast<const unsigned*>(&B2h[st][cb + g][2 * tig]);
                bh[1] = *reinterpret_cast<const unsigned*>(&B2h[st][cb + g][2 * tig + 8]);
                bl[0] = *reinterpret_cast<const unsigned*>(&B2l[st][cb + g][2 * tig]);
                bl[1] = *reinterpret_cast<const unsigned*>(&B2l[st][cb + g][2 * tig + 8]);
                mma3(c[nt], ah, al, bh, bl);
            }
        }
    }

    float* __restrict__ S = g_s + (size_t)bz * N_ * N_;
#pragma unroll
    for (int nt = 0; nt < 4; nt++) {
#pragma unroll
        for (int eh = 0; eh < 2; eh++) {
            const int n = n0 + wm * 16 + g + eh * 8;
            const int m = m0 + wn * 32 + nt * 8 + 2 * tig;
            if (n < N_ && m < N_)
                *reinterpret_cast<float2*>(&S[(size_t)n * N_ + m]) =
                    make_float2(c[nt][eh * 2], c[nt][eh * 2 + 1]);
        }
    }
}

// ---------------------------------------------------------------------------
__global__ __launch_bounds__(256) void softmax_kernel() {
    const int w = blockIdx.x * 8 + (threadIdx.x >> 5);
    const int lane = threadIdx.x & 31;
    if (w >= B_ * H_ * N_) return;
    const float* __restrict__ row = g_s + (size_t)w * N_;
    __nv_bfloat16* __restrict__ rh = g_sh + (size_t)w * N_;
    __nv_bfloat16* __restrict__ rl = g_sl + (size_t)w * N_;

    float v[7];
    float mx = -3.4e38f;
#pragma unroll
    for (int i = 0; i < 7; i++) {
        const int cc = lane + i * 32;
        v[i] = (cc < N_) ? row[cc] : -3.4e38f;
        mx = fmaxf(mx, v[i]);
    }
#pragma unroll
    for (int o = 16; o; o >>= 1) mx = fmaxf(mx, __shfl_xor_sync(0xffffffffu, mx, o));
    float s = 0.f;
#pragma unroll
    for (int i = 0; i < 7; i++) {
        const int cc = lane + i * 32;
        v[i] = (cc < N_) ? __expf(v[i] - mx) : 0.f;
        s += v[i];
    }
#pragma unroll
    for (int o = 16; o; o >>= 1) s += __shfl_xor_sync(0xffffffffu, s, o);
    const float inv = 1.0f / s;
#pragma unroll
    for (int i = 0; i < 7; i++) {
        const int cc = lane + i * 32;
        if (cc < N_) {
            unsigned short hh, ll;
            split_bf(v[i] * inv, hh, ll);
            rh[cc] = __ushort_as_bfloat16(hh);
            rl[cc] = __ushort_as_bfloat16(ll);
        }
    }
}

// ---------------------------------------------------------------------------
// O = A @ V (R11 + dead-tile guards).
// ---------------------------------------------------------------------------
__global__ __launch_bounds__(256) void av_mma() {
    __shared__ unsigned Ahs[2][64][12], Als[2][64][12];
    __shared__ __nv_bfloat16 B2h[2][64][18], B2l[2][64][18];

    const int bz = blockIdx.z;
    const int b = bz >> 2, h = bz & 3;
    const __nv_bfloat16* __restrict__ Ph = g_sh + (size_t)bz * N_ * N_;
    const __nv_bfloat16* __restrict__ Pl = g_sl + (size_t)bz * N_ * N_;
    const __nv_bfloat16* __restrict__ Vh = g_vh + (size_t)bz * N_ * D_;
    const __nv_bfloat16* __restrict__ Vl = g_vl + (size_t)bz * N_ * D_;

    const int n0 = blockIdx.y * 64;
    const int d0 = blockIdx.x * 64;
    const int tid = threadIdx.x;
    const int wid = tid >> 5, lane = tid & 31;
    const int g = lane >> 2, tig = lane & 3;
    const int wm = wid & 3, wn = wid >> 2;

    const int lr = tid >> 2, lq = (tid & 3) * 4, k2 = (tid & 3) * 2;
    const int lk = tid >> 4, lc = (tid & 15) * 4;

    const bool wvalid = (n0 + wm * 16 < N_);

    float c[4][4] = {};

    uint2 rah, ral, rbh, rbl;
    {
        rah = make_uint2(0, 0); ral = make_uint2(0, 0);
        rbh = make_uint2(0, 0); rbl = make_uint2(0, 0);
        if (n0 + lr < N_ && lq + 3 < N_) {
            const size_t e = (size_t)(n0 + lr) * N_ + lq;
            rah = *reinterpret_cast<const uint2*>(&Ph[e]);
            ral = *reinterpret_cast<const uint2*>(&Pl[e]);
        }
        if (lk < N_ && d0 + lc + 3 < D_) {
            const size_t e = (size_t)lk * D_ + d0 + lc;
            rbh = *reinterpret_cast<const uint2*>(&Vh[e]);
            rbl = *reinterpret_cast<const uint2*>(&Vl[e]);
        }
    }
    for (int ci = 0; ci < 13; ci++) {
        const int st = ci & 1;
        *reinterpret_cast<uint2*>(&Ahs[st][lr][k2]) = rah;
        *reinterpret_cast<uint2*>(&Als[st][lr][k2]) = ral;
        {
            const __nv_bfloat16* ph = reinterpret_cast<const __nv_bfloat16*>(&rbh);
            const __nv_bfloat16* pl = reinterpret_cast<const __nv_bfloat16*>(&rbl);
#pragma unroll
            for (int j = 0; j < 4; j++) {
                B2h[st][lc + j][lk] = ph[j];
                B2l[st][lc + j][lk] = pl[j];
            }
        }
        __syncthreads();

        if (ci + 1 < 13) {
            const int k0 = (ci + 1) * 16;
            rah = make_uint2(0, 0); ral = make_uint2(0, 0);
            rbh = make_uint2(0, 0); rbl = make_uint2(0, 0);
            if (n0 + lr < N_ && k0 + lq + 3 < N_) {
                const size_t e = (size_t)(n0 + lr) * N_ + k0 + lq;
                rah = *reinterpret_cast<const uint2*>(&Ph[e]);
                ral = *reinterpret_cast<const uint2*>(&Pl[e]);
            }
            if (k0 + lk < N_ && d0 + lc + 3 < D_) {
                const size_t e = (size_t)(k0 + lk) * D_ + d0 + lc;
                rbh = *reinterpret_cast<const uint2*>(&Vh[e]);
                rbl = *reinterpret_cast<const uint2*>(&Vl[e]);
            }
        }

        if (wvalid) {
            unsigned ah[4], al[4];
            const int rb = wm * 16;
            ah[0] = Ahs[st][rb + g][tig];     al[0] = Als[st][rb + g][tig];
            ah[1] = Ahs[st][rb + g + 8][tig]; al[1] = Als[st][rb + g + 8][tig];
            ah[2] = Ahs[st][rb + g][tig + 4]; al[2] = Als[st][rb + g][tig + 4];
            ah[3] = Ahs[st][rb + g + 8][tig + 4];
            al[3] = Als[st][rb + g + 8][tig + 4];
#pragma unroll
            for (int nt = 0; nt < 4; nt++) {
                const int cb = wn * 32 + nt * 8;
                if (d0 + cb >= D_) continue;
                unsigned bh[2], bl[2];
                bh[0] = *reinterpret_cast<const unsigned*>(&B2h[st][cb + g][2 * tig]);
                bh[1] = *reinterpret_cast<const unsigned*>(&B2h[st][cb + g][2 * tig + 8]);
                bl[0] = *reinterpret_cast<const unsigned*>(&B2l[st][cb + g][2 * tig]);
                bl[1] = *reinterpret_cast<const unsigned*>(&B2l[st][cb + g][2 * tig + 8]);
                mma3(c[nt], ah, al, bh, bl);
            }
        }
    }

#pragma unroll
    for (int nt = 0; nt < 4; nt++) {
#pragma unroll
        for (int eh = 0; eh < 2; eh++) {
            const int n = n0 + wm * 16 + g + eh * 8;
            const int d = d0 + wn * 32 + nt * 8 + 2 * tig;
            if (n < N_ && d < D_) {
                unsigned Hp, Lp;
                split_pack(c[nt][eh * 2], c[nt][eh * 2 + 1], Hp, Lp);
                const size_t off = ((size_t)b * N_ + n) * C_ + h * D_ + d;
                *reinterpret_cast<unsigned*>(&g_aoh[off]) = Hp;
                *reinterpret_cast<unsigned*>(&g_aol[off]) = Lp;
            }
        }
    }
}

// ---------------------------------------------------------------------------
extern "C" void kernel_launch(void* const* d_in, const int* in_sizes, int n_in,
                              void* d_out, int out_size) {
    const float* x  = (const float*)d_in[0];
    const float* Wq = (const float*)d_in[1];
    const float* bq = (const float*)d_in[2];
    const float* Wk = (const float*)d_in[3];
    const float* bk = (const float*)d_in[4];
    const float* Wv = (const float*)d_in[5];
    const float* bv = (const float*)d_in[6];
    const float* Wo = (const float*)d_in[7];
    const float* bo = (const float*)d_in[8];
    const float* rh = (const float*)d_in[9];
    const float* rw = (const float*)d_in[10];
    float* out = (float*)d_out;

    cudaFuncSetAttribute(proj_mma2, cudaFuncAttributeMaxDynamicSharedMemorySize,
                         pj::SMEM_BYTES);

    const int n4x = M_ * C_ / 4;
    const int n4w = C_ * C_ / 4;
    split_arr<<<(n4x + 255) / 256, 256>>>(x, 0, n4x);
    split_arr<<<(n4w + 255) / 256, 256>>>(Wq, 1, n4w);
    split_arr<<<(n4w + 255) / 256, 256>>>(Wk, 2, n4w);
    split_arr<<<(n4w + 255) / 256, 256>>>(Wv, 3, n4w);
    split_arr<<<(n4w + 255) / 256, 256>>>(Wo, 4, n4w);

    build_cp<<<(H_ * N_ * D_ + 255) / 256, 256>>>(rh, rw);

    dim3 gproj(C_ / 112, M_ / 128);  // (7, 392)
    proj_mma2<<<gproj, 256, pj::SMEM_BYTES>>>(bq, nullptr, 0, 0, 0);
    proj_mma2<<<gproj, 256, pj::SMEM_BYTES>>>(bk, nullptr, 1, 1, 0);
    proj_mma2<<<gproj, 256, pj::SMEM_BYTES>>>(bv, nullptr, 2, 2, 0);

    dim3 gatt(4, 4, B_ * H_);
    scores_mma<<<gatt, 256>>>();
    softmax_kernel<<<(B_ * H_ * N_ + 7) / 8, 256>>>();
    av_mma<<<gatt, 256>>>();

    proj_mma2<<<gproj, 256, pj::SMEM_BYTES>>>(bo, out, 3, 3, 1);
}